// round 14
// baseline (speedup 1.0000x reference)
#include <cuda_runtime.h>
#include <cuda_fp16.h>
#include <math_constants.h>
#include <cstdint>

// ---------------- problem constants ----------------
#define N_FEAT 6272      // 8 * 28 * 28
#define M_BANK 30000
#define M_PAD  30720     // 240 tiles of 128
#define D_DIM  128
#define BATCH  8
#define PH     28
#define PW     28
#define IMG    224

// ---------------- GEMM tiling ----------------
#define TILE_M 128
#define TILE_N 128
#define M_TILES 49               // 6272 / 128
#define SPLIT  6
#define TILES_PER_SPLIT 40       // 240 / 6  (even: unroll x2 + peeled tail)
#define PITCH  272               // 17 x 16B: conflict-free ldmatrix, no swizzle ALU

// ---------------- SMEM layout ----------------
#define SMEM_M2   0                               // 2 x 128 floats = 1024 B
#define SMEM_A    1024                            // 128 x 272 B = 34816
#define ABUF_BYTES (TILE_M * PITCH)
#define SMEM_B0   (1024 + ABUF_BYTES)             // 35840
#define BBUF_BYTES (TILE_N * PITCH)               // 34816
#define SMEM_TOTAL (SMEM_B0 + 2 * BBUF_BYTES)     // 105472

// ---------------- device scratch ----------------
__device__ __align__(16) __half g_Ah[(size_t)N_FEAT * D_DIM];
__device__ __align__(16) __half g_Bh[(size_t)M_PAD * D_DIM];
__device__ float        g_m2p[M_PAD];             // ||m||^2 (+inf for pad)
__device__ float        g_f2[N_FEAT];
__device__ unsigned int g_nn[N_FEAT];             // fkey(min of m2 - 2*dot)

// ---------------- asm helpers ----------------
__device__ __forceinline__ uint32_t smem_to_u32(const void* p) {
    uint32_t a;
    asm("{ .reg .u64 t; cvta.to.shared.u64 t, %1; cvt.u32.u64 %0, t; }" : "=r"(a) : "l"(p));
    return a;
}
#define CP_ASYNC16(dst, src) \
    asm volatile("cp.async.cg.shared.global [%0], [%1], 16;" :: "r"(dst), "l"(src) : "memory")
#define CP_COMMIT() asm volatile("cp.async.commit_group;" ::: "memory")
#define CP_WAIT(n)  asm volatile("cp.async.wait_group %0;" :: "n"(n) : "memory")
#define LDSM4(r, addr) \
    asm volatile("ldmatrix.sync.aligned.m8n8.x4.shared.b16 {%0,%1,%2,%3}, [%4];" \
        : "=r"((r)[0]), "=r"((r)[1]), "=r"((r)[2]), "=r"((r)[3]) : "r"(addr))
#define MMA16816(c, a, bb0, bb1) \
    asm volatile("mma.sync.aligned.m16n8k16.row.col.f32.f16.f16.f32 " \
        "{%0,%1,%2,%3}, {%4,%5,%6,%7}, {%8,%9}, {%0,%1,%2,%3};" \
        : "+f"((c)[0]), "+f"((c)[1]), "+f"((c)[2]), "+f"((c)[3]) \
        : "r"((a)[0]), "r"((a)[1]), "r"((a)[2]), "r"((a)[3]), "r"(bb0), "r"(bb1))

// ---- order-preserving float <-> uint map ----
__device__ __forceinline__ unsigned int fkey(float f) {
    unsigned int b = __float_as_uint(f);
    return (b & 0x80000000u) ? ~b : (b | 0x80000000u);
}
__device__ __forceinline__ float fdecode(unsigned int k) {
    unsigned int b = (k & 0x80000000u) ? (k ^ 0x80000000u) : ~k;
    return __uint_as_float(b);
}

// ---------------- prep: fp16 convert + fp32 norms, 8 rows/warp (MLP=8) ----------------
__global__ void k_prep(const float* __restrict__ feat, const float* __restrict__ mem) {
    int w    = (blockIdx.x * blockDim.x + threadIdx.x) >> 5;
    int lane = threadIdx.x & 31;
    int k0   = lane * 4;
    int r0   = w * 8;
    if (r0 < M_PAD) {
        bool ok = r0 < M_BANK;   // M_BANK, M_PAD divisible by 8
        const float4 z4 = make_float4(0.f, 0.f, 0.f, 0.f);
        float4 v[8];
        float  s[8];
        #pragma unroll
        for (int j = 0; j < 8; j++)
            v[j] = ok ? *reinterpret_cast<const float4*>(mem + (size_t)(r0 + j) * D_DIM + k0) : z4;
        #pragma unroll
        for (int j = 0; j < 8; j++) {
            __half2* d = reinterpret_cast<__half2*>(g_Bh + (size_t)(r0 + j) * D_DIM + k0);
            d[0] = __floats2half2_rn(v[j].x, v[j].y);
            d[1] = __floats2half2_rn(v[j].z, v[j].w);
            s[j] = v[j].x*v[j].x + v[j].y*v[j].y + v[j].z*v[j].z + v[j].w*v[j].w;
        }
        #pragma unroll
        for (int o = 16; o; o >>= 1) {
            #pragma unroll
            for (int j = 0; j < 8; j++) s[j] += __shfl_xor_sync(0xffffffffu, s[j], o);
        }
        if (lane == 0) {
            #pragma unroll
            for (int j = 0; j < 8; j++) g_m2p[r0 + j] = ok ? s[j] : CUDART_INF_F;
        }
    } else {
        int f0 = r0 - M_PAD;
        if (f0 < N_FEAT) {   // N_FEAT divisible by 8
            float4 v[8];
            float  s[8];
            #pragma unroll
            for (int j = 0; j < 8; j++)
                v[j] = *reinterpret_cast<const float4*>(feat + (size_t)(f0 + j) * D_DIM + k0);
            #pragma unroll
            for (int j = 0; j < 8; j++) {
                __half2* d = reinterpret_cast<__half2*>(g_Ah + (size_t)(f0 + j) * D_DIM + k0);
                d[0] = __floats2half2_rn(v[j].x, v[j].y);
                d[1] = __floats2half2_rn(v[j].z, v[j].w);
                s[j] = v[j].x*v[j].x + v[j].y*v[j].y + v[j].z*v[j].z + v[j].w*v[j].w;
            }
            #pragma unroll
            for (int o = 16; o; o >>= 1) {
                #pragma unroll
                for (int j = 0; j < 8; j++) s[j] += __shfl_xor_sync(0xffffffffu, s[j], o);
            }
            if (lane == 0) {
                #pragma unroll
                for (int j = 0; j < 8; j++) {
                    g_f2[f0 + j] = s[j];
                    g_nn[f0 + j] = 0xFF800000u;  // fkey(+inf)
                }
            }
        }
    }
}

// B-tile (+ m2 slice) prefetch via cp.async into pitch-272 SMEM (128 threads)
__device__ __forceinline__ void load_B_tile(uint32_t sbB, uint32_t sbM2, int tileIdx, int tid) {
    const size_t c0 = (size_t)tileIdx * TILE_N;
    #pragma unroll
    for (int i = 0; i < 16; i++) {
        int idx = tid + i * 128;        // 0..2047
        int row = idx >> 4;
        int c   = idx & 15;
        uint32_t dst = sbB + row * PITCH + (uint32_t)(c << 4);
        const void* src = g_Bh + (c0 + row) * D_DIM + c * 8;
        CP_ASYNC16(dst, src);
    }
    if (tid < 32) {
        const void* src = g_m2p + c0 + tid * 4;
        CP_ASYNC16(sbM2 + tid * 16, src);
    }
}

// ---------------- main HMMA fp16 GEMM + row-min (R8 skeleton, x2 unrolled buffers) ----------------
// 128 threads = 4 warps in 2(m) x 2(n) grid; warp tile 64x64; 2 CTAs/SM.
__global__ void __launch_bounds__(128, 2)
k_gemm() {
    extern __shared__ __align__(1024) char smem[];
    const uint32_t sb = smem_to_u32(smem);
    const uint32_t sA = sb + SMEM_A;
    const int tid  = threadIdx.x;
    const int lane = tid & 31;
    const int wid  = tid >> 5;
    const int wm   = wid >> 1;   // 0..1
    const int wn   = wid & 1;    // 0..1
    const int r0   = blockIdx.x * TILE_M;
    const int tile0 = blockIdx.y * TILES_PER_SPLIT;

    // ---- resident A tile: 2048 16B chunks, pitch-272 linear ----
    #pragma unroll
    for (int i = 0; i < 16; i++) {
        int idx = tid + i * 128;
        int row = idx >> 4;
        int c   = idx & 15;
        uint32_t dst = sA + row * PITCH + (uint32_t)(c << 4);
        const void* src = g_Ah + (size_t)(r0 + row) * D_DIM + c * 8;
        CP_ASYNC16(dst, src);
    }
    load_B_tile(sb + SMEM_B0, sb + SMEM_M2, tile0, tid);
    CP_COMMIT();

    // ---- per-thread ldmatrix base addresses (ks offset folds to immediate) ----
    const uint32_t hi16 = ((uint32_t)(lane >> 4)) << 4;
    uint32_t aAddr[4];
    #pragma unroll
    for (int mt = 0; mt < 4; mt++) {
        int row = wm * 64 + mt * 16 + (lane & 15);
        aAddr[mt] = sA + row * PITCH + hi16;
    }
    const uint32_t bHi16 = (((uint32_t)(lane >> 3)) & 1u) << 4;
    uint32_t bAddr0[4];   // compile-time-selected buffer bases
    #pragma unroll
    for (int bt = 0; bt < 4; bt++) {
        int n = wn * 64 + bt * 16 + (lane & 7) + ((lane & 16) >> 1);
        bAddr0[bt] = sb + SMEM_B0 + (uint32_t)(n * PITCH) + bHi16;
    }
    const float* m2s0 = reinterpret_cast<const float*>(smem + SMEM_M2) + wn * 64 + (lane & 3) * 2;

    float minv[8] = {CUDART_INF_F, CUDART_INF_F, CUDART_INF_F, CUDART_INF_F,
                     CUDART_INF_F, CUDART_INF_F, CUDART_INF_F, CUDART_INF_F};

    // One tile body; BUF is a compile-time 0/1, PREFETCH is uniform.
#define TILE_BODY(T, BUF, PREFETCH)                                                   \
    {                                                                                 \
        if (PREFETCH) {                                                               \
            load_B_tile(sb + SMEM_B0 + (uint32_t)((BUF) ^ 1) * BBUF_BYTES,            \
                        sb + SMEM_M2 + (uint32_t)((BUF) ^ 1) * 512,                   \
                        tile0 + (T) + 1, tid);                                        \
            CP_COMMIT();                                                              \
            CP_WAIT(1);                                                               \
        } else {                                                                      \
            CP_WAIT(0);                                                               \
        }                                                                             \
        __syncthreads();                                                              \
        float2 mm[8];                                                                 \
        _Pragma("unroll")                                                             \
        for (int nt = 0; nt < 8; nt++)                                                \
            mm[nt] = *reinterpret_cast<const float2*>(m2s0 + (BUF) * 128 + nt * 8);   \
        float acc[4][8][4] = {};                                                      \
        _Pragma("unroll")                                                             \
        for (int ks = 0; ks < 8; ks++) {                                              \
            uint32_t a[4][4];                                                         \
            _Pragma("unroll")                                                         \
            for (int mt = 0; mt < 4; mt++)                                            \
                LDSM4(a[mt], aAddr[mt] + (uint32_t)(ks * 32));                        \
            _Pragma("unroll")                                                         \
            for (int bt = 0; bt < 4; bt++) {                                          \
                uint32_t b[4];                                                        \
                LDSM4(b, bAddr0[bt] + (uint32_t)((BUF) * BBUF_BYTES + ks * 32));      \
                _Pragma("unroll")                                                     \
                for (int mt = 0; mt < 4; mt++) {                                      \
                    MMA16816(acc[mt][2*bt],   a[mt], b[0], b[1]);                     \
                    MMA16816(acc[mt][2*bt+1], a[mt], b[2], b[3]);                     \
                }                                                                     \
            }                                                                         \
        }                                                                             \
        __syncthreads();                                                              \
        _Pragma("unroll")                                                             \
        for (int nt = 0; nt < 8; nt++) {                                              \
            _Pragma("unroll")                                                         \
            for (int mt = 0; mt < 4; mt++) {                                          \
                float d0 = fmaf(-2.f, acc[mt][nt][0], mm[nt].x);                      \
                float d1 = fmaf(-2.f, acc[mt][nt][1], mm[nt].y);                      \
                float d2 = fmaf(-2.f, acc[mt][nt][2], mm[nt].x);                      \
                float d3 = fmaf(-2.f, acc[mt][nt][3], mm[nt].y);                      \
                minv[mt * 2 + 0] = fminf(minv[mt * 2 + 0], fminf(d0, d1));            \
                minv[mt * 2 + 1] = fminf(minv[mt * 2 + 1], fminf(d2, d3));            \
            }                                                                         \
        }                                                                             \
    }

    // 19 double-iterations (t = 0..37), then peeled tail t = 38, 39.
    for (int tt = 0; tt < (TILES_PER_SPLIT - 2) / 2; tt++) {
        int t = tt * 2;
        TILE_BODY(t,     0, true);
        TILE_BODY(t + 1, 1, true);
    }
    TILE_BODY(TILES_PER_SPLIT - 2, 0, true);
    TILE_BODY(TILES_PER_SPLIT - 1, 1, false);
#undef TILE_BODY

    // reduce across the 4 lanes sharing each row, then atomicMin
    #pragma unroll
    for (int i = 0; i < 8; i++) {
        float v = minv[i];
        v = fminf(v, __shfl_xor_sync(0xffffffffu, v, 1));
        v = fminf(v, __shfl_xor_sync(0xffffffffu, v, 2));
        if ((lane & 3) == 0) {
            int row = r0 + wm * 64 + (i >> 1) * 16 + (i & 1) * 8 + (lane >> 2);
            atomicMin(&g_nn[row], fkey(v));
        }
    }
}

// ---------------- merged post: image scores + bilinear upsample ----------------
#define UP_BLOCKS ((BATCH * IMG * IMG) / 256)   // 1568
__device__ __forceinline__ float patch_val(int i) {
    return fdecode(g_nn[i]) + g_f2[i];
}
__global__ void k_post(float* __restrict__ scores, float* __restrict__ up) {
    int bid = blockIdx.x;
    if (bid < UP_BLOCKS) {
        int idx = bid * 256 + threadIdx.x;
        int x = idx % IMG;
        int y = (idx / IMG) % IMG;
        int b = idx / (IMG * IMG);

        const float scale = (float)PH / (float)IMG;
        float sy = (y + 0.5f) * scale - 0.5f;
        float sx = (x + 0.5f) * scale - 0.5f;
        int   y0 = (int)floorf(sy);
        int   x0 = (int)floorf(sx);
        float wy = sy - (float)y0;
        float wx = sx - (float)x0;
        int y0c = min(max(y0, 0), PH - 1);
        int y1c = min(max(y0 + 1, 0), PH - 1);
        int x0c = min(max(x0, 0), PW - 1);
        int x1c = min(max(x0 + 1, 0), PW - 1);

        int base = b * PH * PW;
        float v00 = patch_val(base + y0c * PW + x0c);
        float v01 = patch_val(base + y0c * PW + x1c);
        float v10 = patch_val(base + y1c * PW + x0c);
        float v11 = patch_val(base + y1c * PW + x1c);
        float v0 = v00 + (v01 - v00) * wx;
        float v1 = v10 + (v11 - v10) * wx;
        up[idx] = v0 + (v1 - v0) * wy;
    } else {
        __shared__ float red[256];
        int b = bid - UP_BLOCKS;
        float m = -CUDART_INF_F;
        for (int t = threadIdx.x; t < PH * PW; t += 256)
            m = fmaxf(m, patch_val(b * PH * PW + t));
        red[threadIdx.x] = m;
        __syncthreads();
        for (int s = 128; s; s >>= 1) {
            if (threadIdx.x < s) red[threadIdx.x] = fmaxf(red[threadIdx.x], red[threadIdx.x + s]);
            __syncthreads();
        }
        if (threadIdx.x == 0) scores[b] = red[0];
    }
}

extern "C" void kernel_launch(void* const* d_in, const int* in_sizes, int n_in,
                              void* d_out, int out_size) {
    const float* feat = (const float*)d_in[0];
    const float* mem  = (const float*)d_in[1];
    float* out    = (float*)d_out;
    float* scores = out;
    float* up     = out + (out_size - BATCH * IMG * IMG);

    static int configured = 0;
    if (!configured) {
        cudaFuncSetAttribute(k_gemm, cudaFuncAttributeMaxDynamicSharedMemorySize, SMEM_TOTAL);
        configured = 1;
    }

    // 1) fp16 convert + norms (eight rows per warp)
    {
        long long warps = ((long long)M_PAD + N_FEAT) / 8;
        int blocks = (int)((warps * 32 + 255) / 256);
        k_prep<<<blocks, 256>>>(feat, mem);
    }
    // 2) fp16 HMMA GEMM + row-min
    {
        dim3 grid(M_TILES, SPLIT);
        k_gemm<<<grid, 128, SMEM_TOTAL>>>();
    }
    // 3) image scores + bilinear upsample (one launch)
    k_post<<<UP_BLOCKS + BATCH, 256>>>(scores, up);
}

// round 15
// speedup vs baseline: 1.1091x; 1.1091x over previous
#include <cuda_runtime.h>
#include <cuda_fp16.h>
#include <math_constants.h>
#include <cstdint>

// ---------------- problem constants ----------------
#define N_FEAT 6272      // 8 * 28 * 28
#define M_BANK 30000
#define M_PAD  30720     // 240 tiles of 128
#define D_DIM  128
#define BATCH  8
#define PH     28
#define PW     28
#define IMG    224

// ---------------- GEMM tiling ----------------
#define TILE_M 128
#define TILE_N 128
#define M_TILES 49               // 6272 / 128
#define SPLIT  6
#define TILES_PER_SPLIT 40       // 240 / 6  (compile-time trip count)
#define PITCH  272               // 17 x 16B: conflict-free ldmatrix, no swizzle ALU

// ---------------- SMEM layout ----------------
#define SMEM_M2   0                               // 2 x 128 floats = 1024 B
#define SMEM_A    1024                            // 128 x 272 B = 34816
#define ABUF_BYTES (TILE_M * PITCH)
#define SMEM_B0   (1024 + ABUF_BYTES)             // 35840
#define BBUF_BYTES (TILE_N * PITCH)               // 34816
#define SMEM_TOTAL (SMEM_B0 + 2 * BBUF_BYTES)     // 105472

// ---------------- device scratch ----------------
__device__ __align__(16) __half g_Ah[(size_t)N_FEAT * D_DIM];
__device__ __align__(16) __half g_Bh[(size_t)M_PAD * D_DIM];
__device__ float        g_m2p[M_PAD];             // ||m||^2 (+inf for pad)
__device__ float        g_f2[N_FEAT];
__device__ unsigned int g_nn[N_FEAT];             // fkey(min of m2 - 2*dot)

// ---------------- asm helpers ----------------
__device__ __forceinline__ uint32_t smem_to_u32(const void* p) {
    uint32_t a;
    asm("{ .reg .u64 t; cvta.to.shared.u64 t, %1; cvt.u32.u64 %0, t; }" : "=r"(a) : "l"(p));
    return a;
}
#define CP_ASYNC16(dst, src) \
    asm volatile("cp.async.cg.shared.global [%0], [%1], 16;" :: "r"(dst), "l"(src) : "memory")
#define CP_COMMIT() asm volatile("cp.async.commit_group;" ::: "memory")
#define CP_WAIT(n)  asm volatile("cp.async.wait_group %0;" :: "n"(n) : "memory")
#define LDSM4(r, addr) \
    asm volatile("ldmatrix.sync.aligned.m8n8.x4.shared.b16 {%0,%1,%2,%3}, [%4];" \
        : "=r"((r)[0]), "=r"((r)[1]), "=r"((r)[2]), "=r"((r)[3]) : "r"(addr))
#define MMA16816(c, a, bb0, bb1) \
    asm volatile("mma.sync.aligned.m16n8k16.row.col.f32.f16.f16.f32 " \
        "{%0,%1,%2,%3}, {%4,%5,%6,%7}, {%8,%9}, {%0,%1,%2,%3};" \
        : "+f"((c)[0]), "+f"((c)[1]), "+f"((c)[2]), "+f"((c)[3]) \
        : "r"((a)[0]), "r"((a)[1]), "r"((a)[2]), "r"((a)[3]), "r"(bb0), "r"(bb1))

// ---- order-preserving float <-> uint map ----
__device__ __forceinline__ unsigned int fkey(float f) {
    unsigned int b = __float_as_uint(f);
    return (b & 0x80000000u) ? ~b : (b | 0x80000000u);
}
__device__ __forceinline__ float fdecode(unsigned int k) {
    unsigned int b = (k & 0x80000000u) ? (k ^ 0x80000000u) : ~k;
    return __uint_as_float(b);
}

// ---------------- prep: fp16 convert + fp32 norms, 4 rows/warp (MLP=4) ----------------
__global__ void k_prep(const float* __restrict__ feat, const float* __restrict__ mem) {
    int w    = (blockIdx.x * blockDim.x + threadIdx.x) >> 5;
    int lane = threadIdx.x & 31;
    int k0   = lane * 4;
    int r0   = w * 4;
    if (r0 < M_PAD) {
        bool ok = r0 < M_BANK;
        const float4 z4 = make_float4(0.f, 0.f, 0.f, 0.f);
        float4 v[4];
        float  s[4];
        #pragma unroll
        for (int j = 0; j < 4; j++)
            v[j] = ok ? *reinterpret_cast<const float4*>(mem + (size_t)(r0 + j) * D_DIM + k0) : z4;
        #pragma unroll
        for (int j = 0; j < 4; j++) {
            __half2* d = reinterpret_cast<__half2*>(g_Bh + (size_t)(r0 + j) * D_DIM + k0);
            d[0] = __floats2half2_rn(v[j].x, v[j].y);
            d[1] = __floats2half2_rn(v[j].z, v[j].w);
            s[j] = v[j].x*v[j].x + v[j].y*v[j].y + v[j].z*v[j].z + v[j].w*v[j].w;
        }
        #pragma unroll
        for (int o = 16; o; o >>= 1) {
            #pragma unroll
            for (int j = 0; j < 4; j++) s[j] += __shfl_xor_sync(0xffffffffu, s[j], o);
        }
        if (lane == 0) {
            #pragma unroll
            for (int j = 0; j < 4; j++) g_m2p[r0 + j] = ok ? s[j] : CUDART_INF_F;
        }
    } else {
        int f0 = r0 - M_PAD;
        if (f0 < N_FEAT) {
            float4 v[4];
            float  s[4];
            #pragma unroll
            for (int j = 0; j < 4; j++)
                v[j] = *reinterpret_cast<const float4*>(feat + (size_t)(f0 + j) * D_DIM + k0);
            #pragma unroll
            for (int j = 0; j < 4; j++) {
                __half2* d = reinterpret_cast<__half2*>(g_Ah + (size_t)(f0 + j) * D_DIM + k0);
                d[0] = __floats2half2_rn(v[j].x, v[j].y);
                d[1] = __floats2half2_rn(v[j].z, v[j].w);
                s[j] = v[j].x*v[j].x + v[j].y*v[j].y + v[j].z*v[j].z + v[j].w*v[j].w;
            }
            #pragma unroll
            for (int o = 16; o; o >>= 1) {
                #pragma unroll
                for (int j = 0; j < 4; j++) s[j] += __shfl_xor_sync(0xffffffffu, s[j], o);
            }
            if (lane == 0) {
                #pragma unroll
                for (int j = 0; j < 4; j++) {
                    g_f2[f0 + j] = s[j];
                    g_nn[f0 + j] = 0xFF800000u;  // fkey(+inf)
                }
            }
        }
    }
}

// B-tile (+ m2 slice) prefetch via cp.async into pitch-272 SMEM (128 threads)
__device__ __forceinline__ void load_B_tile(uint32_t sbB, uint32_t sbM2, int tileIdx, int tid) {
    const size_t c0 = (size_t)tileIdx * TILE_N;
    #pragma unroll
    for (int i = 0; i < 16; i++) {
        int idx = tid + i * 128;        // 0..2047
        int row = idx >> 4;
        int c   = idx & 15;
        uint32_t dst = sbB + row * PITCH + (uint32_t)(c << 4);
        const void* src = g_Bh + (c0 + row) * D_DIM + c * 8;
        CP_ASYNC16(dst, src);
    }
    if (tid < 32) {
        const void* src = g_m2p + c0 + tid * 4;
        CP_ASYNC16(sbM2 + tid * 16, src);
    }
}

// ---------------- main HMMA fp16 GEMM + row-min (R13 frozen) ----------------
// 128 threads = 4 warps in 2(m) x 2(n) grid; warp tile 64x64; 2 CTAs/SM.
__global__ void __launch_bounds__(128, 2)
k_gemm() {
    extern __shared__ __align__(1024) char smem[];
    const uint32_t sb = smem_to_u32(smem);
    const uint32_t sA = sb + SMEM_A;
    const int tid  = threadIdx.x;
    const int lane = tid & 31;
    const int wid  = tid >> 5;
    const int wm   = wid >> 1;   // 0..1
    const int wn   = wid & 1;    // 0..1
    const int r0   = blockIdx.x * TILE_M;
    const int tile0 = blockIdx.y * TILES_PER_SPLIT;

    // ---- resident A tile: 2048 16B chunks, pitch-272 linear ----
    #pragma unroll
    for (int i = 0; i < 16; i++) {
        int idx = tid + i * 128;
        int row = idx >> 4;
        int c   = idx & 15;
        uint32_t dst = sA + row * PITCH + (uint32_t)(c << 4);
        const void* src = g_Ah + (size_t)(r0 + row) * D_DIM + c * 8;
        CP_ASYNC16(dst, src);
    }
    load_B_tile(sb + SMEM_B0, sb + SMEM_M2, tile0, tid);
    CP_COMMIT();

    // ---- per-thread ldmatrix base addresses (ks offset folds to immediate) ----
    const uint32_t hi16 = ((uint32_t)(lane >> 4)) << 4;
    uint32_t aAddr[4];
    #pragma unroll
    for (int mt = 0; mt < 4; mt++) {
        int row = wm * 64 + mt * 16 + (lane & 15);
        aAddr[mt] = sA + row * PITCH + hi16;
    }
    const uint32_t bHi16 = (((uint32_t)(lane >> 3)) & 1u) << 4;
    uint32_t bRel[4];
    #pragma unroll
    for (int bt = 0; bt < 4; bt++) {
        int n = wn * 64 + bt * 16 + (lane & 7) + ((lane & 16) >> 1);
        bRel[bt] = (uint32_t)(n * PITCH) + bHi16;
    }

    float minv[8] = {CUDART_INF_F, CUDART_INF_F, CUDART_INF_F, CUDART_INF_F,
                     CUDART_INF_F, CUDART_INF_F, CUDART_INF_F, CUDART_INF_F};

    for (int t = 0; t < TILES_PER_SPLIT; t++) {
        if (t + 1 < TILES_PER_SPLIT) {
            load_B_tile(sb + SMEM_B0 + (uint32_t)((t + 1) & 1) * BBUF_BYTES,
                        sb + SMEM_M2 + (uint32_t)((t + 1) & 1) * 512,
                        tile0 + t + 1, tid);
            CP_COMMIT();
            CP_WAIT(1);
        } else {
            CP_WAIT(0);
        }
        __syncthreads();

        const uint32_t bb = sb + SMEM_B0 + (uint32_t)(t & 1) * BBUF_BYTES;
        uint32_t bAddr[4];
        #pragma unroll
        for (int bt = 0; bt < 4; bt++) bAddr[bt] = bb + bRel[bt];

        // hoist m2 values to registers (SMEM reads done before bottom sync)
        const float* m2s = reinterpret_cast<const float*>(smem + SMEM_M2 + (t & 1) * 512);
        float2 mm[8];
        #pragma unroll
        for (int nt = 0; nt < 8; nt++)
            mm[nt] = *reinterpret_cast<const float2*>(&m2s[wn * 64 + nt * 8 + (lane & 3) * 2]);

        float acc[4][8][4] = {};

        #pragma unroll
        for (int ks = 0; ks < 8; ks++) {
            uint32_t a[4][4];
            #pragma unroll
            for (int mt = 0; mt < 4; mt++)
                LDSM4(a[mt], aAddr[mt] + (uint32_t)(ks * 32));
            #pragma unroll
            for (int bt = 0; bt < 4; bt++) {
                uint32_t b[4];
                LDSM4(b, bAddr[bt] + (uint32_t)(ks * 32));
                #pragma unroll
                for (int mt = 0; mt < 4; mt++) {
                    MMA16816(acc[mt][2*bt],   a[mt], b[0], b[1]);
                    MMA16816(acc[mt][2*bt+1], a[mt], b[2], b[3]);
                }
            }
        }
        __syncthreads();   // all SMEM reads of this tile complete; next prefetch may overwrite

        // deferred reg-only epilogue: overlaps with next iteration's prefetch/wait
        #pragma unroll
        for (int nt = 0; nt < 8; nt++) {
            #pragma unroll
            for (int mt = 0; mt < 4; mt++) {
                float d0 = fmaf(-2.f, acc[mt][nt][0], mm[nt].x);
                float d1 = fmaf(-2.f, acc[mt][nt][1], mm[nt].y);
                float d2 = fmaf(-2.f, acc[mt][nt][2], mm[nt].x);
                float d3 = fmaf(-2.f, acc[mt][nt][3], mm[nt].y);
                minv[mt * 2 + 0] = fminf(minv[mt * 2 + 0], fminf(d0, d1));
                minv[mt * 2 + 1] = fminf(minv[mt * 2 + 1], fminf(d2, d3));
            }
        }
    }

    // reduce across the 4 lanes sharing each row, then atomicMin
    #pragma unroll
    for (int i = 0; i < 8; i++) {
        float v = minv[i];
        v = fminf(v, __shfl_xor_sync(0xffffffffu, v, 1));
        v = fminf(v, __shfl_xor_sync(0xffffffffu, v, 2));
        if ((lane & 3) == 0) {
            int row = r0 + wm * 64 + (i >> 1) * 16 + (i & 1) * 8 + (lane >> 2);
            atomicMin(&g_nn[row], fkey(v));
        }
    }
}

// ---------------- merged post: 3D grid, no div/mod ----------------
// grid (1, IMG+1, BATCH), 224 threads. y<IMG: one output row; y==IMG: batch max.
__device__ __forceinline__ float patch_val(int i) {
    return fdecode(g_nn[i]) + g_f2[i];
}
__global__ void k_post(float* __restrict__ scores, float* __restrict__ up) {
    const int b = blockIdx.z;
    const int y = blockIdx.y;
    if (y < IMG) {
        const int x = threadIdx.x;

        const float scale = (float)PH / (float)IMG;
        float sy = (y + 0.5f) * scale - 0.5f;
        float sx = (x + 0.5f) * scale - 0.5f;
        int   y0 = (int)floorf(sy);
        int   x0 = (int)floorf(sx);
        float wy = sy - (float)y0;
        float wx = sx - (float)x0;
        int y0c = min(max(y0, 0), PH - 1);
        int y1c = min(max(y0 + 1, 0), PH - 1);
        int x0c = min(max(x0, 0), PW - 1);
        int x1c = min(max(x0 + 1, 0), PW - 1);

        int base = b * PH * PW;
        float v00 = patch_val(base + y0c * PW + x0c);
        float v01 = patch_val(base + y0c * PW + x1c);
        float v10 = patch_val(base + y1c * PW + x0c);
        float v11 = patch_val(base + y1c * PW + x1c);
        float v0 = v00 + (v01 - v00) * wx;
        float v1 = v10 + (v11 - v10) * wx;
        up[(b * IMG + y) * IMG + x] = v0 + (v1 - v0) * wy;
    } else {
        // per-batch max over 784 patch scores, 224 threads = 7 warps
        const int tid  = threadIdx.x;
        const int lane = tid & 31;
        const int w    = tid >> 5;
        __shared__ float red[7];
        float m = -CUDART_INF_F;
        for (int t = tid; t < PH * PW; t += 224)
            m = fmaxf(m, patch_val(b * PH * PW + t));
        #pragma unroll
        for (int o = 16; o; o >>= 1) m = fmaxf(m, __shfl_xor_sync(0xffffffffu, m, o));
        if (lane == 0) red[w] = m;
        __syncthreads();
        if (tid == 0) {
            float mm = red[0];
            #pragma unroll
            for (int i = 1; i < 7; i++) mm = fmaxf(mm, red[i]);
            scores[b] = mm;
        }
    }
}

extern "C" void kernel_launch(void* const* d_in, const int* in_sizes, int n_in,
                              void* d_out, int out_size) {
    const float* feat = (const float*)d_in[0];
    const float* mem  = (const float*)d_in[1];
    float* out    = (float*)d_out;
    float* scores = out;
    float* up     = out + (out_size - BATCH * IMG * IMG);

    static int configured = 0;
    if (!configured) {
        cudaFuncSetAttribute(k_gemm, cudaFuncAttributeMaxDynamicSharedMemorySize, SMEM_TOTAL);
        configured = 1;
    }

    // 1) fp16 convert + norms (four rows per warp)
    {
        long long warps = ((long long)M_PAD + N_FEAT) / 4;
        int blocks = (int)((warps * 32 + 255) / 256);
        k_prep<<<blocks, 256>>>(feat, mem);
    }
    // 2) fp16 HMMA GEMM + row-min
    {
        dim3 grid(M_TILES, SPLIT);
        k_gemm<<<grid, 128, SMEM_TOTAL>>>();
    }
    // 3) image scores + bilinear upsample (one launch, 3D grid)
    {
        dim3 grid(1, IMG + 1, BATCH);
        k_post<<<grid, 224>>>(scores, up);
    }
}

// round 16
// speedup vs baseline: 1.1167x; 1.0068x over previous
#include <cuda_runtime.h>
#include <cuda_fp16.h>
#include <math_constants.h>
#include <cstdint>

// ---------------- problem constants ----------------
#define N_FEAT 6272      // 8 * 28 * 28
#define M_BANK 30000
#define M_PAD  30720     // 240 tiles of 128
#define D_DIM  128
#define BATCH  8
#define PH     28
#define PW     28
#define IMG    224

// ---------------- GEMM tiling ----------------
#define TILE_M 128
#define TILE_N 128
#define M_TILES 49               // 6272 / 128
#define SPLIT  6
#define TILES_PER_SPLIT 40       // 240 / 6  (compile-time trip count)
#define PITCH  272               // 17 x 16B: conflict-free ldmatrix, no swizzle ALU

// ---------------- SMEM layout ----------------
#define SMEM_M2   0                               // 2 x 128 floats = 1024 B
#define SMEM_A    1024                            // 128 x 272 B = 34816
#define ABUF_BYTES (TILE_M * PITCH)
#define SMEM_B0   (1024 + ABUF_BYTES)             // 35840
#define BBUF_BYTES (TILE_N * PITCH)               // 34816
#define SMEM_TOTAL (SMEM_B0 + 2 * BBUF_BYTES)     // 105472

// ---------------- device scratch ----------------
__device__ __align__(16) __half g_Ah[(size_t)N_FEAT * D_DIM];
__device__ __align__(16) __half g_Bh[(size_t)M_PAD * D_DIM];
__device__ float        g_m2p[M_PAD];             // ||m||^2 (+inf for pad)
__device__ float        g_f2[N_FEAT];
__device__ unsigned int g_nn[N_FEAT];             // fkey(min of m2 - 2*dot)

// ---------------- asm helpers ----------------
__device__ __forceinline__ uint32_t smem_to_u32(const void* p) {
    uint32_t a;
    asm("{ .reg .u64 t; cvta.to.shared.u64 t, %1; cvt.u32.u64 %0, t; }" : "=r"(a) : "l"(p));
    return a;
}
#define CP_ASYNC16(dst, src) \
    asm volatile("cp.async.cg.shared.global [%0], [%1], 16;" :: "r"(dst), "l"(src) : "memory")
#define CP_COMMIT() asm volatile("cp.async.commit_group;" ::: "memory")
#define CP_WAIT(n)  asm volatile("cp.async.wait_group %0;" :: "n"(n) : "memory")
#define LDSM4(r, addr) \
    asm volatile("ldmatrix.sync.aligned.m8n8.x4.shared.b16 {%0,%1,%2,%3}, [%4];" \
        : "=r"((r)[0]), "=r"((r)[1]), "=r"((r)[2]), "=r"((r)[3]) : "r"(addr))
#define MMA16816(c, a, bb0, bb1) \
    asm volatile("mma.sync.aligned.m16n8k16.row.col.f32.f16.f16.f32 " \
        "{%0,%1,%2,%3}, {%4,%5,%6,%7}, {%8,%9}, {%0,%1,%2,%3};" \
        : "+f"((c)[0]), "+f"((c)[1]), "+f"((c)[2]), "+f"((c)[3]) \
        : "r"((a)[0]), "r"((a)[1]), "r"((a)[2]), "r"((a)[3]), "r"(bb0), "r"(bb1))

// ---- order-preserving float <-> uint map ----
__device__ __forceinline__ unsigned int fkey(float f) {
    unsigned int b = __float_as_uint(f);
    return (b & 0x80000000u) ? ~b : (b | 0x80000000u);
}
__device__ __forceinline__ float fdecode(unsigned int k) {
    unsigned int b = (k & 0x80000000u) ? (k ^ 0x80000000u) : ~k;
    return __uint_as_float(b);
}

// ---------------- prep: fp16 convert + fp32 norms ----------------
// 4 rows/warp, pairwise: half-warp owns a row, thread converts 8 floats
// (2x LDG.128 -> 1x STG.128), norm tree-reduced over 16 lanes.
__global__ void k_prep(const float* __restrict__ feat, const float* __restrict__ mem) {
    int w    = (blockIdx.x * blockDim.x + threadIdx.x) >> 5;
    int lane = threadIdx.x & 31;
    int half = lane >> 4;            // 0/1: which row of the pair
    int kq   = (lane & 15) * 8;      // 8 floats per thread
    int r0   = w * 4;

    if (r0 < M_PAD) {
        bool ok = r0 < M_BANK;       // M_BANK, M_PAD divisible by 4
        #pragma unroll
        for (int p = 0; p < 2; p++) {
            int row = r0 + p * 2 + half;
            const float4 z4 = make_float4(0.f, 0.f, 0.f, 0.f);
            const float* src = mem + (size_t)row * D_DIM + kq;
            float4 va = ok ? *reinterpret_cast<const float4*>(src)     : z4;
            float4 vb = ok ? *reinterpret_cast<const float4*>(src + 4) : z4;
            __half2 h0 = __floats2half2_rn(va.x, va.y);
            __half2 h1 = __floats2half2_rn(va.z, va.w);
            __half2 h2 = __floats2half2_rn(vb.x, vb.y);
            __half2 h3 = __floats2half2_rn(vb.z, vb.w);
            uint4 pk;
            pk.x = *reinterpret_cast<uint32_t*>(&h0);
            pk.y = *reinterpret_cast<uint32_t*>(&h1);
            pk.z = *reinterpret_cast<uint32_t*>(&h2);
            pk.w = *reinterpret_cast<uint32_t*>(&h3);
            *reinterpret_cast<uint4*>(g_Bh + (size_t)row * D_DIM + kq) = pk;
            float s = va.x*va.x + va.y*va.y + va.z*va.z + va.w*va.w
                    + vb.x*vb.x + vb.y*vb.y + vb.z*vb.z + vb.w*vb.w;
            #pragma unroll
            for (int o = 1; o < 16; o <<= 1) s += __shfl_xor_sync(0xffffffffu, s, o);
            if ((lane & 15) == 0) g_m2p[row] = ok ? s : CUDART_INF_F;
        }
    } else {
        int f0 = r0 - M_PAD;
        if (f0 < N_FEAT) {           // N_FEAT divisible by 4
            #pragma unroll
            for (int p = 0; p < 2; p++) {
                int row = f0 + p * 2 + half;
                const float* src = feat + (size_t)row * D_DIM + kq;
                float4 va = *reinterpret_cast<const float4*>(src);
                float4 vb = *reinterpret_cast<const float4*>(src + 4);
                __half2 h0 = __floats2half2_rn(va.x, va.y);
                __half2 h1 = __floats2half2_rn(va.z, va.w);
                __half2 h2 = __floats2half2_rn(vb.x, vb.y);
                __half2 h3 = __floats2half2_rn(vb.z, vb.w);
                uint4 pk;
                pk.x = *reinterpret_cast<uint32_t*>(&h0);
                pk.y = *reinterpret_cast<uint32_t*>(&h1);
                pk.z = *reinterpret_cast<uint32_t*>(&h2);
                pk.w = *reinterpret_cast<uint32_t*>(&h3);
                *reinterpret_cast<uint4*>(g_Ah + (size_t)row * D_DIM + kq) = pk;
                float s = va.x*va.x + va.y*va.y + va.z*va.z + va.w*va.w
                        + vb.x*vb.x + vb.y*vb.y + vb.z*vb.z + vb.w*vb.w;
                #pragma unroll
                for (int o = 1; o < 16; o <<= 1) s += __shfl_xor_sync(0xffffffffu, s, o);
                if ((lane & 15) == 0) {
                    g_f2[row] = s;
                    g_nn[row] = 0xFF800000u;  // fkey(+inf)
                }
            }
        }
    }
}

// B-tile (+ m2 slice) prefetch via cp.async into pitch-272 SMEM (128 threads)
__device__ __forceinline__ void load_B_tile(uint32_t sbB, uint32_t sbM2, int tileIdx, int tid) {
    const size_t c0 = (size_t)tileIdx * TILE_N;
    #pragma unroll
    for (int i = 0; i < 16; i++) {
        int idx = tid + i * 128;        // 0..2047
        int row = idx >> 4;
        int c   = idx & 15;
        uint32_t dst = sbB + row * PITCH + (uint32_t)(c << 4);
        const void* src = g_Bh + (c0 + row) * D_DIM + c * 8;
        CP_ASYNC16(dst, src);
    }
    if (tid < 32) {
        const void* src = g_m2p + c0 + tid * 4;
        CP_ASYNC16(sbM2 + tid * 16, src);
    }
}

// ---------------- main HMMA fp16 GEMM + row-min (R13 frozen) ----------------
// 128 threads = 4 warps in 2(m) x 2(n) grid; warp tile 64x64; 2 CTAs/SM.
__global__ void __launch_bounds__(128, 2)
k_gemm() {
    extern __shared__ __align__(1024) char smem[];
    const uint32_t sb = smem_to_u32(smem);
    const uint32_t sA = sb + SMEM_A;
    const int tid  = threadIdx.x;
    const int lane = tid & 31;
    const int wid  = tid >> 5;
    const int wm   = wid >> 1;   // 0..1
    const int wn   = wid & 1;    // 0..1
    const int r0   = blockIdx.x * TILE_M;
    const int tile0 = blockIdx.y * TILES_PER_SPLIT;

    // ---- resident A tile: 2048 16B chunks, pitch-272 linear ----
    #pragma unroll
    for (int i = 0; i < 16; i++) {
        int idx = tid + i * 128;
        int row = idx >> 4;
        int c   = idx & 15;
        uint32_t dst = sA + row * PITCH + (uint32_t)(c << 4);
        const void* src = g_Ah + (size_t)(r0 + row) * D_DIM + c * 8;
        CP_ASYNC16(dst, src);
    }
    load_B_tile(sb + SMEM_B0, sb + SMEM_M2, tile0, tid);
    CP_COMMIT();

    // ---- per-thread ldmatrix base addresses (ks offset folds to immediate) ----
    const uint32_t hi16 = ((uint32_t)(lane >> 4)) << 4;
    uint32_t aAddr[4];
    #pragma unroll
    for (int mt = 0; mt < 4; mt++) {
        int row = wm * 64 + mt * 16 + (lane & 15);
        aAddr[mt] = sA + row * PITCH + hi16;
    }
    const uint32_t bHi16 = (((uint32_t)(lane >> 3)) & 1u) << 4;
    uint32_t bRel[4];
    #pragma unroll
    for (int bt = 0; bt < 4; bt++) {
        int n = wn * 64 + bt * 16 + (lane & 7) + ((lane & 16) >> 1);
        bRel[bt] = (uint32_t)(n * PITCH) + bHi16;
    }

    float minv[8] = {CUDART_INF_F, CUDART_INF_F, CUDART_INF_F, CUDART_INF_F,
                     CUDART_INF_F, CUDART_INF_F, CUDART_INF_F, CUDART_INF_F};

    for (int t = 0; t < TILES_PER_SPLIT; t++) {
        if (t + 1 < TILES_PER_SPLIT) {
            load_B_tile(sb + SMEM_B0 + (uint32_t)((t + 1) & 1) * BBUF_BYTES,
                        sb + SMEM_M2 + (uint32_t)((t + 1) & 1) * 512,
                        tile0 + t + 1, tid);
            CP_COMMIT();
            CP_WAIT(1);
        } else {
            CP_WAIT(0);
        }
        __syncthreads();

        const uint32_t bb = sb + SMEM_B0 + (uint32_t)(t & 1) * BBUF_BYTES;
        uint32_t bAddr[4];
        #pragma unroll
        for (int bt = 0; bt < 4; bt++) bAddr[bt] = bb + bRel[bt];

        // hoist m2 values to registers (SMEM reads done before bottom sync)
        const float* m2s = reinterpret_cast<const float*>(smem + SMEM_M2 + (t & 1) * 512);
        float2 mm[8];
        #pragma unroll
        for (int nt = 0; nt < 8; nt++)
            mm[nt] = *reinterpret_cast<const float2*>(&m2s[wn * 64 + nt * 8 + (lane & 3) * 2]);

        float acc[4][8][4] = {};

        #pragma unroll
        for (int ks = 0; ks < 8; ks++) {
            uint32_t a[4][4];
            #pragma unroll
            for (int mt = 0; mt < 4; mt++)
                LDSM4(a[mt], aAddr[mt] + (uint32_t)(ks * 32));
            #pragma unroll
            for (int bt = 0; bt < 4; bt++) {
                uint32_t b[4];
                LDSM4(b, bAddr[bt] + (uint32_t)(ks * 32));
                #pragma unroll
                for (int mt = 0; mt < 4; mt++) {
                    MMA16816(acc[mt][2*bt],   a[mt], b[0], b[1]);
                    MMA16816(acc[mt][2*bt+1], a[mt], b[2], b[3]);
                }
            }
        }
        __syncthreads();   // all SMEM reads of this tile complete; next prefetch may overwrite

        // deferred reg-only epilogue: overlaps with next iteration's prefetch/wait
        #pragma unroll
        for (int nt = 0; nt < 8; nt++) {
            #pragma unroll
            for (int mt = 0; mt < 4; mt++) {
                float d0 = fmaf(-2.f, acc[mt][nt][0], mm[nt].x);
                float d1 = fmaf(-2.f, acc[mt][nt][1], mm[nt].y);
                float d2 = fmaf(-2.f, acc[mt][nt][2], mm[nt].x);
                float d3 = fmaf(-2.f, acc[mt][nt][3], mm[nt].y);
                minv[mt * 2 + 0] = fminf(minv[mt * 2 + 0], fminf(d0, d1));
                minv[mt * 2 + 1] = fminf(minv[mt * 2 + 1], fminf(d2, d3));
            }
        }
    }

    // reduce across the 4 lanes sharing each row, then atomicMin
    #pragma unroll
    for (int i = 0; i < 8; i++) {
        float v = minv[i];
        v = fminf(v, __shfl_xor_sync(0xffffffffu, v, 1));
        v = fminf(v, __shfl_xor_sync(0xffffffffu, v, 2));
        if ((lane & 3) == 0) {
            int row = r0 + wm * 64 + (i >> 1) * 16 + (i & 1) * 8 + (lane >> 2);
            atomicMin(&g_nn[row], fkey(v));
        }
    }
}

// ---------------- merged post: 3D grid, no div/mod ----------------
// grid (1, IMG+1, BATCH), 224 threads. y<IMG: one output row; y==IMG: batch max.
__device__ __forceinline__ float patch_val(int i) {
    return fdecode(g_nn[i]) + g_f2[i];
}
__global__ void k_post(float* __restrict__ scores, float* __restrict__ up) {
    const int b = blockIdx.z;
    const int y = blockIdx.y;
    if (y < IMG) {
        const int x = threadIdx.x;

        const float scale = (float)PH / (float)IMG;
        float sy = (y + 0.5f) * scale - 0.5f;
        float sx = (x + 0.5f) * scale - 0.5f;
        int   y0 = (int)floorf(sy);
        int   x0 = (int)floorf(sx);
        float wy = sy - (float)y0;
        float wx = sx - (float)x0;
        int y0c = min(max(y0, 0), PH - 1);
        int y1c = min(max(y0 + 1, 0), PH - 1);
        int x0c = min(max(x0, 0), PW - 1);
        int x1c = min(max(x0 + 1, 0), PW - 1);

        int base = b * PH * PW;
        float v00 = patch_val(base + y0c * PW + x0c);
        float v01 = patch_val(base + y0c * PW + x1c);
        float v10 = patch_val(base + y1c * PW + x0c);
        float v11 = patch_val(base + y1c * PW + x1c);
        float v0 = v00 + (v01 - v00) * wx;
        float v1 = v10 + (v11 - v10) * wx;
        up[(b * IMG + y) * IMG + x] = v0 + (v1 - v0) * wy;
    } else {
        // per-batch max over 784 patch scores, 224 threads = 7 warps
        const int tid  = threadIdx.x;
        const int lane = tid & 31;
        const int w    = tid >> 5;
        __shared__ float red[7];
        float m = -CUDART_INF_F;
        for (int t = tid; t < PH * PW; t += 224)
            m = fmaxf(m, patch_val(b * PH * PW + t));
        #pragma unroll
        for (int o = 16; o; o >>= 1) m = fmaxf(m, __shfl_xor_sync(0xffffffffu, m, o));
        if (lane == 0) red[w] = m;
        __syncthreads();
        if (tid == 0) {
            float mm = red[0];
            #pragma unroll
            for (int i = 1; i < 7; i++) mm = fmaxf(mm, red[i]);
            scores[b] = mm;
        }
    }
}

extern "C" void kernel_launch(void* const* d_in, const int* in_sizes, int n_in,
                              void* d_out, int out_size) {
    const float* feat = (const float*)d_in[0];
    const float* mem  = (const float*)d_in[1];
    float* out    = (float*)d_out;
    float* scores = out;
    float* up     = out + (out_size - BATCH * IMG * IMG);

    static int configured = 0;
    if (!configured) {
        cudaFuncSetAttribute(k_gemm, cudaFuncAttributeMaxDynamicSharedMemorySize, SMEM_TOTAL);
        configured = 1;
    }

    // 1) fp16 convert + norms (four rows per warp, pairwise)
    {
        long long warps = ((long long)M_PAD + N_FEAT) / 4;
        int blocks = (int)((warps * 32 + 255) / 256);
        k_prep<<<blocks, 256>>>(feat, mem);
    }
    // 2) fp16 HMMA GEMM + row-min
    {
        dim3 grid(M_TILES, SPLIT);
        k_gemm<<<grid, 128, SMEM_TOTAL>>>();
    }
    // 3) image scores + bilinear upsample (one launch, 3D grid)
    {
        dim3 grid(1, IMG + 1, BATCH);
        k_post<<<grid, 224>>>(scores, up);
    }
}